// round 9
// baseline (speedup 1.0000x reference)
#include <cuda_runtime.h>
#include <math.h>

// ============================================================================
// RBRLoss — R9: 16-row tiles (2x warp count -> 32+ warps/SM resident).
// R8 taught: per-warp MLP > 8 loads costs registers and occupancy and LOSES;
// warps/SM was the real limiter (grid had only 21 warps/SM of work).
// Distance body identical in style to R7 (simple unroll, 8 LDG.128/iter),
// but each warp now owns 16 rows (4 macro-iters). PGD on lanes 0-15,
// 20 op / 10 pe fixed iterations.
// ============================================================================

#define TPB 128

__device__ __forceinline__ float sq4(const float4 a, const float4 b) {
    float d0 = a.x - b.x, d1 = a.y - b.y, d2 = a.z - b.z, d3 = a.w - b.w;
    return d0 * d0 + d1 * d1 + d2 * d2 + d3 * d3;
}

// 8 independent row-sums in 9 shuffles; lane l<8 ends with full sum of value
// index j = 4*bit0(l) + 2*bit1(l) + bit2(l). Writes results to s_cp/s_cn
// (slots are warp-local: wib*16 + rb + (j&3)).
__device__ __forceinline__ void reduce8_store(float v[8], int lane, int wib,
                                              int rb, float* s_cp, float* s_cn) {
    {
        const bool hi = (lane & 1);
#pragma unroll
        for (int i = 0; i < 4; i++) {
            float give = hi ? v[i] : v[i + 4];
            float got  = __shfl_xor_sync(0xffffffffu, give, 1);
            v[i] = (hi ? v[i + 4] : v[i]) + got;
        }
    }
    {
        const bool hi = (lane & 2);
#pragma unroll
        for (int i = 0; i < 2; i++) {
            float give = hi ? v[i] : v[i + 2];
            float got  = __shfl_xor_sync(0xffffffffu, give, 2);
            v[i] = (hi ? v[i + 2] : v[i]) + got;
        }
    }
    {
        const bool hi = (lane & 4);
        float give = hi ? v[0] : v[1];
        float got  = __shfl_xor_sync(0xffffffffu, give, 4);
        v[0] = (hi ? v[1] : v[0]) + got;
    }
    v[0] += __shfl_xor_sync(0xffffffffu, v[0], 8);
    v[0] += __shfl_xor_sync(0xffffffffu, v[0], 16);

    if (lane < 8) {
        const int j = ((lane & 1) << 2) | (lane & 2) | ((lane >> 2) & 1);
        const float c = sqrtf(v[0]);
        const int slot = wib * 16 + rb + (j & 3);
        if (j < 4) s_cp[slot] = c;
        else       s_cn[slot] = c;
    }
}

__global__ void __launch_bounds__(TPB, 8)
rbr_kernel(const float* __restrict__ x,
           const float* __restrict__ Xp,
           const float* __restrict__ Xn,
           float* __restrict__ out,
           int N, int ntiles, int out_size)
{
    __shared__ float s_cp[64];   // 16 rows per warp, 4 warps
    __shared__ float s_cn[64];

    const int tid  = threadIdx.x;
    const int lane = tid & 31;
    const int wib  = tid >> 5;
    const int tile = blockIdx.x * 4 + wib;
    if (tile >= ntiles) return;

    const int row0 = tile * 16;
    const float4 xa = reinterpret_cast<const float4*>(x)[lane];

    const float4* __restrict__ Xp4 = reinterpret_cast<const float4*>(Xp);
    const float4* __restrict__ Xn4 = reinterpret_cast<const float4*>(Xn);

    if (row0 + 16 <= N) {
        // ---- fast path: full 16-row tile, fully unrolled, no clamps ----
        const int base = row0 * 32 + lane;
#pragma unroll
        for (int it4 = 0; it4 < 4; ++it4) {
            const int rb = it4 * 4;
            const int b0 = base + (rb + 0) * 32;
            const int b1 = base + (rb + 1) * 32;
            const int b2 = base + (rb + 2) * 32;
            const int b3 = base + (rb + 3) * 32;

            const float4 p0 = Xp4[b0];
            const float4 p1 = Xp4[b1];
            const float4 p2 = Xp4[b2];
            const float4 p3 = Xp4[b3];
            const float4 n0 = Xn4[b0];
            const float4 n1 = Xn4[b1];
            const float4 n2 = Xn4[b2];
            const float4 n3 = Xn4[b3];

            float v[8];
            v[0] = sq4(xa, p0); v[1] = sq4(xa, p1); v[2] = sq4(xa, p2); v[3] = sq4(xa, p3);
            v[4] = sq4(xa, n0); v[5] = sq4(xa, n1); v[6] = sq4(xa, n2); v[7] = sq4(xa, n3);

            reduce8_store(v, lane, wib, rb, s_cp, s_cn);
        }
    } else {
        // ---- generic path: clamped row indices ----
        for (int it4 = 0; it4 < 4; ++it4) {
            const int rb = it4 * 4;
            int g0i = row0 + rb + 0; if (g0i >= N) g0i = N - 1;
            int g1i = row0 + rb + 1; if (g1i >= N) g1i = N - 1;
            int g2i = row0 + rb + 2; if (g2i >= N) g2i = N - 1;
            int g3i = row0 + rb + 3; if (g3i >= N) g3i = N - 1;
            const int b0 = g0i * 32 + lane;
            const int b1 = g1i * 32 + lane;
            const int b2 = g2i * 32 + lane;
            const int b3 = g3i * 32 + lane;

            const float4 p0 = Xp4[b0];
            const float4 p1 = Xp4[b1];
            const float4 p2 = Xp4[b2];
            const float4 p3 = Xp4[b3];
            const float4 n0 = Xn4[b0];
            const float4 n1 = Xn4[b1];
            const float4 n2 = Xn4[b2];
            const float4 n3 = Xn4[b3];

            float v[8];
            v[0] = sq4(xa, p0); v[1] = sq4(xa, p1); v[2] = sq4(xa, p2); v[3] = sq4(xa, p3);
            v[4] = sq4(xa, n0); v[5] = sq4(xa, n1); v[6] = sq4(xa, n2); v[7] = sq4(xa, n3);

            reduce8_store(v, lane, wib, rb, s_cp, s_cn);
        }
    }
    __syncwarp();

    // ---- per-lane fixed-count PGD: lanes 0..15 own rows row0..row0+15 ----
    if (lane >= 16) return;
    const int row = row0 + lane;
    const float cp = s_cp[wib * 16 + lane];
    const float cn = s_cn[wib * 16 + lane];

    const float sigma  = 0.5f;
    const float lr     = 0.03162277660168379f;   // 1/sqrt(1000)
    const float p      = 128.0f;
    const float pm1    = 127.0f;
    const float sqrt_p = 11.313708498984761f;    // sqrt(128)
    const float opC    = pm1 * logf(0.5f);
    const float ze     = 1.000001f;              // ZETA + EPS_PE^2
    const float pe_rad = 0.08838834764831845f;   // 1/sqrt(128)

    float v0 = 0.0f, v1 = 0.0f, u0 = 0.0f, u1 = 0.0f;

#pragma unroll 1
    for (int it = 0; it < 10; ++it) {
        // op step
        {
            float d   = v1 + sigma;
            float r   = cp - v0;
            float id  = __fdividef(1.0f, d);
            float id2 = id * id;
            float g0  = -r * id2;
            float g1  = id * (1.0f - (r * r) * id2);
            float w0  = fmaxf(v0 - lr * g0, 0.0f);
            float w1  = fmaxf(v1 - lr * g1, 0.0f);
            float n2  = w0 * w0 + w1 * w1;
            float sc  = (n2 > 1.0f) ? rsqrtf(n2) : 1.0f;
            v0 = w0 * sc;
            v1 = w1 * sc;
        }
        // pe step (inside guard inactive on nominal path)
        {
            float d    = u1 + sigma;
            float s    = cn + sqrt_p * u0;
            float inside = ((ze - p * (u0 * u0)) - u1 * u1) * (1.0f / 127.0f);
            inside = fmaxf(inside, 1e-12f);
            float f    = sqrtf(inside);
            float fs   = f + sigma;
            float iff  = __fdividef(1.0f, f * fs);
            float id   = __fdividef(1.0f, d);
            float id2  = id * id;
            float s2   = s * s;
            float g0   = (-sqrt_p) * s * id2 - (p * u0) * iff;
            float g1   = id * (s2 * id2 - 1.0f) + u1 * iff;
            float w0   = fmaxf(u0 - lr * g0, 0.0f);
            float w1   = fmaxf(u1 - lr * g1, 0.0f);
            float n2   = w0 * w0 + w1 * w1;
            float sc   = (n2 > pe_rad * pe_rad) ? (pe_rad * rsqrtf(n2)) : 1.0f;
            u0 = w0 * sc;
            u1 = w1 * sc;
        }
    }
#pragma unroll 1
    for (int it = 0; it < 10; ++it) {   // op only: total 20 op iterations
        float d   = v1 + sigma;
        float r   = cp - v0;
        float id  = __fdividef(1.0f, d);
        float id2 = id * id;
        float g0  = -r * id2;
        float g1  = id * (1.0f - (r * r) * id2);
        float w0  = fmaxf(v0 - lr * g0, 0.0f);
        float w1  = fmaxf(v1 - lr * g1, 0.0f);
        float n2  = w0 * w0 + w1 * w1;
        float sc  = (n2 > 1.0f) ? rsqrtf(n2) : 1.0f;
        v0 = w0 * sc;
        v1 = w1 * sc;
    }

    // ---- final losses, full precision ----
    if (row < N) {
        float d  = v1 + sigma;
        float r  = cp - v0;
        float d2 = d * d;
        float numer = (logf(d) + (r * r) / (2.0f * d2)) + opC;

        float du  = u1 + sigma;
        float s   = cn + sqrt_p * u0;
        float inside = ((ze - p * (u0 * u0)) - u1 * u1) / pm1;
        inside = fmaxf(inside, 1e-12f);
        float f   = sqrtf(inside);
        float fs  = f + sigma;
        float du2 = du * du;
        float denom = ((-logf(du)) - (s * s) / (2.0f * du2)) - pm1 * logf(fs);

        if (row < out_size)          out[row]         = numer - denom;
        if (N + row < out_size)      out[N + row]     = denom;
        if (2 * N + row < out_size)  out[2 * N + row] = numer;
    }
}

extern "C" void kernel_launch(void* const* d_in, const int* in_sizes, int n_in,
                              void* d_out, int out_size) {
    const float* x  = (const float*)d_in[0];
    // d_in[1] = X_feas (unused on the non-empty path)
    const float* Xp = (const float*)d_in[2];
    const float* Xn = (const float*)d_in[3];

    int d = in_sizes[0];             // 128
    int N = in_sizes[2] / d;         // 100000
    if (N <= 0) return;

    int ntiles = (N + 15) / 16;      // 16-row tiles, one per warp
    int nb = (ntiles + 3) / 4;       // 4 warps per 128-thread block
    if (nb < 1) nb = 1;

    rbr_kernel<<<nb, TPB>>>(x, Xp, Xn, (float*)d_out, N, ntiles, out_size);
}

// round 10
// speedup vs baseline: 1.0682x; 1.0682x over previous
#include <cuda_runtime.h>
#include <math.h>

// ============================================================================
// RBRLoss — R9: 16-row tiles (2x warp count -> 32+ warps/SM resident).
// R8 taught: per-warp MLP > 8 loads costs registers and occupancy and LOSES;
// warps/SM was the real limiter (grid had only 21 warps/SM of work).
// Distance body identical in style to R7 (simple unroll, 8 LDG.128/iter),
// but each warp now owns 16 rows (4 macro-iters). PGD on lanes 0-15,
// 20 op / 10 pe fixed iterations.
// ============================================================================

#define TPB 128

__device__ __forceinline__ float sq4(const float4 a, const float4 b) {
    float d0 = a.x - b.x, d1 = a.y - b.y, d2 = a.z - b.z, d3 = a.w - b.w;
    return d0 * d0 + d1 * d1 + d2 * d2 + d3 * d3;
}

// 8 independent row-sums in 9 shuffles; lane l<8 ends with full sum of value
// index j = 4*bit0(l) + 2*bit1(l) + bit2(l). Writes results to s_cp/s_cn
// (slots are warp-local: wib*16 + rb + (j&3)).
__device__ __forceinline__ void reduce8_store(float v[8], int lane, int wib,
                                              int rb, float* s_cp, float* s_cn) {
    {
        const bool hi = (lane & 1);
#pragma unroll
        for (int i = 0; i < 4; i++) {
            float give = hi ? v[i] : v[i + 4];
            float got  = __shfl_xor_sync(0xffffffffu, give, 1);
            v[i] = (hi ? v[i + 4] : v[i]) + got;
        }
    }
    {
        const bool hi = (lane & 2);
#pragma unroll
        for (int i = 0; i < 2; i++) {
            float give = hi ? v[i] : v[i + 2];
            float got  = __shfl_xor_sync(0xffffffffu, give, 2);
            v[i] = (hi ? v[i + 2] : v[i]) + got;
        }
    }
    {
        const bool hi = (lane & 4);
        float give = hi ? v[0] : v[1];
        float got  = __shfl_xor_sync(0xffffffffu, give, 4);
        v[0] = (hi ? v[1] : v[0]) + got;
    }
    v[0] += __shfl_xor_sync(0xffffffffu, v[0], 8);
    v[0] += __shfl_xor_sync(0xffffffffu, v[0], 16);

    if (lane < 8) {
        const int j = ((lane & 1) << 2) | (lane & 2) | ((lane >> 2) & 1);
        const float c = sqrtf(v[0]);
        const int slot = wib * 16 + rb + (j & 3);
        if (j < 4) s_cp[slot] = c;
        else       s_cn[slot] = c;
    }
}

__global__ void __launch_bounds__(TPB, 8)
rbr_kernel(const float* __restrict__ x,
           const float* __restrict__ Xp,
           const float* __restrict__ Xn,
           float* __restrict__ out,
           int N, int ntiles, int out_size)
{
    __shared__ float s_cp[64];   // 16 rows per warp, 4 warps
    __shared__ float s_cn[64];

    const int tid  = threadIdx.x;
    const int lane = tid & 31;
    const int wib  = tid >> 5;
    const int tile = blockIdx.x * 4 + wib;
    if (tile >= ntiles) return;

    const int row0 = tile * 16;
    const float4 xa = reinterpret_cast<const float4*>(x)[lane];

    const float4* __restrict__ Xp4 = reinterpret_cast<const float4*>(Xp);
    const float4* __restrict__ Xn4 = reinterpret_cast<const float4*>(Xn);

    if (row0 + 16 <= N) {
        // ---- fast path: full 16-row tile, fully unrolled, no clamps ----
        const int base = row0 * 32 + lane;
#pragma unroll
        for (int it4 = 0; it4 < 4; ++it4) {
            const int rb = it4 * 4;
            const int b0 = base + (rb + 0) * 32;
            const int b1 = base + (rb + 1) * 32;
            const int b2 = base + (rb + 2) * 32;
            const int b3 = base + (rb + 3) * 32;

            const float4 p0 = Xp4[b0];
            const float4 p1 = Xp4[b1];
            const float4 p2 = Xp4[b2];
            const float4 p3 = Xp4[b3];
            const float4 n0 = Xn4[b0];
            const float4 n1 = Xn4[b1];
            const float4 n2 = Xn4[b2];
            const float4 n3 = Xn4[b3];

            float v[8];
            v[0] = sq4(xa, p0); v[1] = sq4(xa, p1); v[2] = sq4(xa, p2); v[3] = sq4(xa, p3);
            v[4] = sq4(xa, n0); v[5] = sq4(xa, n1); v[6] = sq4(xa, n2); v[7] = sq4(xa, n3);

            reduce8_store(v, lane, wib, rb, s_cp, s_cn);
        }
    } else {
        // ---- generic path: clamped row indices ----
        for (int it4 = 0; it4 < 4; ++it4) {
            const int rb = it4 * 4;
            int g0i = row0 + rb + 0; if (g0i >= N) g0i = N - 1;
            int g1i = row0 + rb + 1; if (g1i >= N) g1i = N - 1;
            int g2i = row0 + rb + 2; if (g2i >= N) g2i = N - 1;
            int g3i = row0 + rb + 3; if (g3i >= N) g3i = N - 1;
            const int b0 = g0i * 32 + lane;
            const int b1 = g1i * 32 + lane;
            const int b2 = g2i * 32 + lane;
            const int b3 = g3i * 32 + lane;

            const float4 p0 = Xp4[b0];
            const float4 p1 = Xp4[b1];
            const float4 p2 = Xp4[b2];
            const float4 p3 = Xp4[b3];
            const float4 n0 = Xn4[b0];
            const float4 n1 = Xn4[b1];
            const float4 n2 = Xn4[b2];
            const float4 n3 = Xn4[b3];

            float v[8];
            v[0] = sq4(xa, p0); v[1] = sq4(xa, p1); v[2] = sq4(xa, p2); v[3] = sq4(xa, p3);
            v[4] = sq4(xa, n0); v[5] = sq4(xa, n1); v[6] = sq4(xa, n2); v[7] = sq4(xa, n3);

            reduce8_store(v, lane, wib, rb, s_cp, s_cn);
        }
    }
    __syncwarp();

    // ---- per-lane fixed-count PGD: lanes 0..15 own rows row0..row0+15 ----
    if (lane >= 16) return;
    const int row = row0 + lane;
    const float cp = s_cp[wib * 16 + lane];
    const float cn = s_cn[wib * 16 + lane];

    const float sigma  = 0.5f;
    const float lr     = 0.03162277660168379f;   // 1/sqrt(1000)
    const float p      = 128.0f;
    const float pm1    = 127.0f;
    const float sqrt_p = 11.313708498984761f;    // sqrt(128)
    const float opC    = pm1 * logf(0.5f);
    const float ze     = 1.000001f;              // ZETA + EPS_PE^2
    const float pe_rad = 0.08838834764831845f;   // 1/sqrt(128)

    float v0 = 0.0f, v1 = 0.0f, u0 = 0.0f, u1 = 0.0f;

#pragma unroll 1
    for (int it = 0; it < 10; ++it) {
        // op step
        {
            float d   = v1 + sigma;
            float r   = cp - v0;
            float id  = __fdividef(1.0f, d);
            float id2 = id * id;
            float g0  = -r * id2;
            float g1  = id * (1.0f - (r * r) * id2);
            float w0  = fmaxf(v0 - lr * g0, 0.0f);
            float w1  = fmaxf(v1 - lr * g1, 0.0f);
            float n2  = w0 * w0 + w1 * w1;
            float sc  = (n2 > 1.0f) ? rsqrtf(n2) : 1.0f;
            v0 = w0 * sc;
            v1 = w1 * sc;
        }
        // pe step (inside guard inactive on nominal path)
        {
            float d    = u1 + sigma;
            float s    = cn + sqrt_p * u0;
            float inside = ((ze - p * (u0 * u0)) - u1 * u1) * (1.0f / 127.0f);
            inside = fmaxf(inside, 1e-12f);
            float f    = sqrtf(inside);
            float fs   = f + sigma;
            float iff  = __fdividef(1.0f, f * fs);
            float id   = __fdividef(1.0f, d);
            float id2  = id * id;
            float s2   = s * s;
            float g0   = (-sqrt_p) * s * id2 - (p * u0) * iff;
            float g1   = id * (s2 * id2 - 1.0f) + u1 * iff;
            float w0   = fmaxf(u0 - lr * g0, 0.0f);
            float w1   = fmaxf(u1 - lr * g1, 0.0f);
            float n2   = w0 * w0 + w1 * w1;
            float sc   = (n2 > pe_rad * pe_rad) ? (pe_rad * rsqrtf(n2)) : 1.0f;
            u0 = w0 * sc;
            u1 = w1 * sc;
        }
    }
#pragma unroll 1
    for (int it = 0; it < 10; ++it) {   // op only: total 20 op iterations
        float d   = v1 + sigma;
        float r   = cp - v0;
        float id  = __fdividef(1.0f, d);
        float id2 = id * id;
        float g0  = -r * id2;
        float g1  = id * (1.0f - (r * r) * id2);
        float w0  = fmaxf(v0 - lr * g0, 0.0f);
        float w1  = fmaxf(v1 - lr * g1, 0.0f);
        float n2  = w0 * w0 + w1 * w1;
        float sc  = (n2 > 1.0f) ? rsqrtf(n2) : 1.0f;
        v0 = w0 * sc;
        v1 = w1 * sc;
    }

    // ---- final losses, full precision ----
    if (row < N) {
        float d  = v1 + sigma;
        float r  = cp - v0;
        float d2 = d * d;
        float numer = (logf(d) + (r * r) / (2.0f * d2)) + opC;

        float du  = u1 + sigma;
        float s   = cn + sqrt_p * u0;
        float inside = ((ze - p * (u0 * u0)) - u1 * u1) / pm1;
        inside = fmaxf(inside, 1e-12f);
        float f   = sqrtf(inside);
        float fs  = f + sigma;
        float du2 = du * du;
        float denom = ((-logf(du)) - (s * s) / (2.0f * du2)) - pm1 * logf(fs);

        if (row < out_size)          out[row]         = numer - denom;
        if (N + row < out_size)      out[N + row]     = denom;
        if (2 * N + row < out_size)  out[2 * N + row] = numer;
    }
}

extern "C" void kernel_launch(void* const* d_in, const int* in_sizes, int n_in,
                              void* d_out, int out_size) {
    const float* x  = (const float*)d_in[0];
    // d_in[1] = X_feas (unused on the non-empty path)
    const float* Xp = (const float*)d_in[2];
    const float* Xn = (const float*)d_in[3];

    int d = in_sizes[0];             // 128
    int N = in_sizes[2] / d;         // 100000
    if (N <= 0) return;

    int ntiles = (N + 15) / 16;      // 16-row tiles, one per warp
    int nb = (ntiles + 3) / 4;       // 4 warps per 128-thread block
    if (nb < 1) nb = 1;

    rbr_kernel<<<nb, TPB>>>(x, Xp, Xn, (float*)d_out, N, ntiles, out_size);
}

// round 11
// speedup vs baseline: 1.0711x; 1.0028x over previous
#include <cuda_runtime.h>
#include <math.h>

// ============================================================================
// RBRLoss — R9: 16-row tiles (2x warp count -> 32+ warps/SM resident).
// R8 taught: per-warp MLP > 8 loads costs registers and occupancy and LOSES;
// warps/SM was the real limiter (grid had only 21 warps/SM of work).
// Distance body identical in style to R7 (simple unroll, 8 LDG.128/iter),
// but each warp now owns 16 rows (4 macro-iters). PGD on lanes 0-15,
// 20 op / 10 pe fixed iterations.
// ============================================================================

#define TPB 128

__device__ __forceinline__ float sq4(const float4 a, const float4 b) {
    float d0 = a.x - b.x, d1 = a.y - b.y, d2 = a.z - b.z, d3 = a.w - b.w;
    return d0 * d0 + d1 * d1 + d2 * d2 + d3 * d3;
}

// 8 independent row-sums in 9 shuffles; lane l<8 ends with full sum of value
// index j = 4*bit0(l) + 2*bit1(l) + bit2(l). Writes results to s_cp/s_cn
// (slots are warp-local: wib*16 + rb + (j&3)).
__device__ __forceinline__ void reduce8_store(float v[8], int lane, int wib,
                                              int rb, float* s_cp, float* s_cn) {
    {
        const bool hi = (lane & 1);
#pragma unroll
        for (int i = 0; i < 4; i++) {
            float give = hi ? v[i] : v[i + 4];
            float got  = __shfl_xor_sync(0xffffffffu, give, 1);
            v[i] = (hi ? v[i + 4] : v[i]) + got;
        }
    }
    {
        const bool hi = (lane & 2);
#pragma unroll
        for (int i = 0; i < 2; i++) {
            float give = hi ? v[i] : v[i + 2];
            float got  = __shfl_xor_sync(0xffffffffu, give, 2);
            v[i] = (hi ? v[i + 2] : v[i]) + got;
        }
    }
    {
        const bool hi = (lane & 4);
        float give = hi ? v[0] : v[1];
        float got  = __shfl_xor_sync(0xffffffffu, give, 4);
        v[0] = (hi ? v[1] : v[0]) + got;
    }
    v[0] += __shfl_xor_sync(0xffffffffu, v[0], 8);
    v[0] += __shfl_xor_sync(0xffffffffu, v[0], 16);

    if (lane < 8) {
        const int j = ((lane & 1) << 2) | (lane & 2) | ((lane >> 2) & 1);
        const float c = sqrtf(v[0]);
        const int slot = wib * 16 + rb + (j & 3);
        if (j < 4) s_cp[slot] = c;
        else       s_cn[slot] = c;
    }
}

__global__ void __launch_bounds__(TPB, 8)
rbr_kernel(const float* __restrict__ x,
           const float* __restrict__ Xp,
           const float* __restrict__ Xn,
           float* __restrict__ out,
           int N, int ntiles, int out_size)
{
    __shared__ float s_cp[64];   // 16 rows per warp, 4 warps
    __shared__ float s_cn[64];

    const int tid  = threadIdx.x;
    const int lane = tid & 31;
    const int wib  = tid >> 5;
    const int tile = blockIdx.x * 4 + wib;
    if (tile >= ntiles) return;

    const int row0 = tile * 16;
    const float4 xa = reinterpret_cast<const float4*>(x)[lane];

    const float4* __restrict__ Xp4 = reinterpret_cast<const float4*>(Xp);
    const float4* __restrict__ Xn4 = reinterpret_cast<const float4*>(Xn);

    if (row0 + 16 <= N) {
        // ---- fast path: full 16-row tile, fully unrolled, no clamps ----
        const int base = row0 * 32 + lane;
#pragma unroll
        for (int it4 = 0; it4 < 4; ++it4) {
            const int rb = it4 * 4;
            const int b0 = base + (rb + 0) * 32;
            const int b1 = base + (rb + 1) * 32;
            const int b2 = base + (rb + 2) * 32;
            const int b3 = base + (rb + 3) * 32;

            const float4 p0 = Xp4[b0];
            const float4 p1 = Xp4[b1];
            const float4 p2 = Xp4[b2];
            const float4 p3 = Xp4[b3];
            const float4 n0 = Xn4[b0];
            const float4 n1 = Xn4[b1];
            const float4 n2 = Xn4[b2];
            const float4 n3 = Xn4[b3];

            float v[8];
            v[0] = sq4(xa, p0); v[1] = sq4(xa, p1); v[2] = sq4(xa, p2); v[3] = sq4(xa, p3);
            v[4] = sq4(xa, n0); v[5] = sq4(xa, n1); v[6] = sq4(xa, n2); v[7] = sq4(xa, n3);

            reduce8_store(v, lane, wib, rb, s_cp, s_cn);
        }
    } else {
        // ---- generic path: clamped row indices ----
        for (int it4 = 0; it4 < 4; ++it4) {
            const int rb = it4 * 4;
            int g0i = row0 + rb + 0; if (g0i >= N) g0i = N - 1;
            int g1i = row0 + rb + 1; if (g1i >= N) g1i = N - 1;
            int g2i = row0 + rb + 2; if (g2i >= N) g2i = N - 1;
            int g3i = row0 + rb + 3; if (g3i >= N) g3i = N - 1;
            const int b0 = g0i * 32 + lane;
            const int b1 = g1i * 32 + lane;
            const int b2 = g2i * 32 + lane;
            const int b3 = g3i * 32 + lane;

            const float4 p0 = Xp4[b0];
            const float4 p1 = Xp4[b1];
            const float4 p2 = Xp4[b2];
            const float4 p3 = Xp4[b3];
            const float4 n0 = Xn4[b0];
            const float4 n1 = Xn4[b1];
            const float4 n2 = Xn4[b2];
            const float4 n3 = Xn4[b3];

            float v[8];
            v[0] = sq4(xa, p0); v[1] = sq4(xa, p1); v[2] = sq4(xa, p2); v[3] = sq4(xa, p3);
            v[4] = sq4(xa, n0); v[5] = sq4(xa, n1); v[6] = sq4(xa, n2); v[7] = sq4(xa, n3);

            reduce8_store(v, lane, wib, rb, s_cp, s_cn);
        }
    }
    __syncwarp();

    // ---- per-lane fixed-count PGD: lanes 0..15 own rows row0..row0+15 ----
    if (lane >= 16) return;
    const int row = row0 + lane;
    const float cp = s_cp[wib * 16 + lane];
    const float cn = s_cn[wib * 16 + lane];

    const float sigma  = 0.5f;
    const float lr     = 0.03162277660168379f;   // 1/sqrt(1000)
    const float p      = 128.0f;
    const float pm1    = 127.0f;
    const float sqrt_p = 11.313708498984761f;    // sqrt(128)
    const float opC    = pm1 * logf(0.5f);
    const float ze     = 1.000001f;              // ZETA + EPS_PE^2
    const float pe_rad = 0.08838834764831845f;   // 1/sqrt(128)

    float v0 = 0.0f, v1 = 0.0f, u0 = 0.0f, u1 = 0.0f;

#pragma unroll 1
    for (int it = 0; it < 10; ++it) {
        // op step
        {
            float d   = v1 + sigma;
            float r   = cp - v0;
            float id  = __fdividef(1.0f, d);
            float id2 = id * id;
            float g0  = -r * id2;
            float g1  = id * (1.0f - (r * r) * id2);
            float w0  = fmaxf(v0 - lr * g0, 0.0f);
            float w1  = fmaxf(v1 - lr * g1, 0.0f);
            float n2  = w0 * w0 + w1 * w1;
            float sc  = (n2 > 1.0f) ? rsqrtf(n2) : 1.0f;
            v0 = w0 * sc;
            v1 = w1 * sc;
        }
        // pe step (inside guard inactive on nominal path)
        {
            float d    = u1 + sigma;
            float s    = cn + sqrt_p * u0;
            float inside = ((ze - p * (u0 * u0)) - u1 * u1) * (1.0f / 127.0f);
            inside = fmaxf(inside, 1e-12f);
            float f    = sqrtf(inside);
            float fs   = f + sigma;
            float iff  = __fdividef(1.0f, f * fs);
            float id   = __fdividef(1.0f, d);
            float id2  = id * id;
            float s2   = s * s;
            float g0   = (-sqrt_p) * s * id2 - (p * u0) * iff;
            float g1   = id * (s2 * id2 - 1.0f) + u1 * iff;
            float w0   = fmaxf(u0 - lr * g0, 0.0f);
            float w1   = fmaxf(u1 - lr * g1, 0.0f);
            float n2   = w0 * w0 + w1 * w1;
            float sc   = (n2 > pe_rad * pe_rad) ? (pe_rad * rsqrtf(n2)) : 1.0f;
            u0 = w0 * sc;
            u1 = w1 * sc;
        }
    }
#pragma unroll 1
    for (int it = 0; it < 10; ++it) {   // op only: total 20 op iterations
        float d   = v1 + sigma;
        float r   = cp - v0;
        float id  = __fdividef(1.0f, d);
        float id2 = id * id;
        float g0  = -r * id2;
        float g1  = id * (1.0f - (r * r) * id2);
        float w0  = fmaxf(v0 - lr * g0, 0.0f);
        float w1  = fmaxf(v1 - lr * g1, 0.0f);
        float n2  = w0 * w0 + w1 * w1;
        float sc  = (n2 > 1.0f) ? rsqrtf(n2) : 1.0f;
        v0 = w0 * sc;
        v1 = w1 * sc;
    }

    // ---- final losses, full precision ----
    if (row < N) {
        float d  = v1 + sigma;
        float r  = cp - v0;
        float d2 = d * d;
        float numer = (logf(d) + (r * r) / (2.0f * d2)) + opC;

        float du  = u1 + sigma;
        float s   = cn + sqrt_p * u0;
        float inside = ((ze - p * (u0 * u0)) - u1 * u1) / pm1;
        inside = fmaxf(inside, 1e-12f);
        float f   = sqrtf(inside);
        float fs  = f + sigma;
        float du2 = du * du;
        float denom = ((-logf(du)) - (s * s) / (2.0f * du2)) - pm1 * logf(fs);

        if (row < out_size)          out[row]         = numer - denom;
        if (N + row < out_size)      out[N + row]     = denom;
        if (2 * N + row < out_size)  out[2 * N + row] = numer;
    }
}

extern "C" void kernel_launch(void* const* d_in, const int* in_sizes, int n_in,
                              void* d_out, int out_size) {
    const float* x  = (const float*)d_in[0];
    // d_in[1] = X_feas (unused on the non-empty path)
    const float* Xp = (const float*)d_in[2];
    const float* Xn = (const float*)d_in[3];

    int d = in_sizes[0];             // 128
    int N = in_sizes[2] / d;         // 100000
    if (N <= 0) return;

    int ntiles = (N + 15) / 16;      // 16-row tiles, one per warp
    int nb = (ntiles + 3) / 4;       // 4 warps per 128-thread block
    if (nb < 1) nb = 1;

    rbr_kernel<<<nb, TPB>>>(x, Xp, Xn, (float*)d_out, N, ntiles, out_size);
}